// round 12
// baseline (speedup 1.0000x reference)
#include <cuda_runtime.h>
#include <cuda_fp16.h>

// EdgeConv: per-edge MLP 20 -> 16 (ReLU+LN) -> 16 (ReLU+LN) -> 4, fp32.
// Layer 1: per-node fp16 partials (y_a = x@W1[0:8]+b1, y_b = x@W1[8:16])
//   gathered per edge + attr@W1c from __constant__; f32x2 math; LN1.
// Layers 2+3: tensor cores. Per warp: [32,16]@[16,16] = 4x mma.m16n8k16.f16,
//   LN2 on distributed C fragments (shfl.bfly in 4-lane groups),
//   [32,16]@[16,4] = 2x mma (C-frag layout == next A-frag layout, no restage).
// W2/W3 fp16 fragments + folded biases precomputed per-lane into g_wfrag.

#define HID 16
#define IN_DIM 20
#define ODIM 4
#define LN_EPS 1e-5f
#define MAX_NODES 131072

// constant layout (float4 units) — only W1 attr rows used by main kernel now
#define OW1 0
#define OB1 80
#define OW2 84
#define OB2 148
#define OW3 152
#define OB3 168
#define CTOT 169

__constant__ float4 cAll[CTOT];
__device__ float g_fold[CTOT * 4];

// Per-node fp16 partials: 2 uint4 (32B) per node per side.
__device__ uint4 g_ya[MAX_NODES * 2];
__device__ uint4 g_yb[MAX_NODES * 2];
__device__ int g_is64;

// Per-lane weight fragments: [32 lanes][4 uint4]
//  v0 = (L2b0, L2b1, L2b2, L2b3)     fp16x2 B-fragments of W2' (g1-folded)
//  v1 = (L3b0, L3b1, b2c0, b2c1)    W3' frags (g2-folded, n-padded) + L2 bias
//  v2 = (b2c2, b2c3, b3c0, b3c1)    L2 bias cols +8, L3 bias
__device__ uint4 g_wfrag[32 * 4];

typedef unsigned long long u64;
union F2u { float2 f; u64 u; };

__device__ __forceinline__ u64 pk(float lo, float hi) { F2u t; t.f.x = lo; t.f.y = hi; return t.u; }
__device__ __forceinline__ u64 dupf(float w) {
    u64 d; asm("mov.b64 %0, {%1, %1};" : "=l"(d) : "f"(w)); return d;
}
__device__ __forceinline__ u64 ffma2(u64 a, u64 b, u64 c) {
    u64 d; asm("fma.rn.f32x2 %0, %1, %2, %3;" : "=l"(d) : "l"(a), "l"(b), "l"(c)); return d;
}
__device__ __forceinline__ u64 fmul2(u64 a, u64 b) {
    u64 d; asm("mul.rn.f32x2 %0, %1, %2;" : "=l"(d) : "l"(a), "l"(b)); return d;
}
__device__ __forceinline__ u64 fadd2(u64 a, u64 b) {
    u64 d; asm("add.rn.f32x2 %0, %1, %2;" : "=l"(d) : "l"(a), "l"(b)); return d;
}
__device__ __forceinline__ u64 frelu2(u64 a) {
    F2u t; t.u = a; t.f.x = fmaxf(t.f.x, 0.f); t.f.y = fmaxf(t.f.y, 0.f); return t.u;
}
__device__ __forceinline__ unsigned packh2(float lo, float hi) {
    __half2 h = __floats2half2_rn(lo, hi);
    return *(unsigned*)&h;
}
__device__ __forceinline__ u64 h2u(unsigned w) {
    __half2 h = *(__half2*)&w;
    float2 f = __half22float2(h);
    return pk(f.x, f.y);
}

__device__ __forceinline__ void mma16816(float& c0, float& c1, float& c2, float& c3,
                                         unsigned a0, unsigned a1, unsigned a2, unsigned a3,
                                         unsigned b0, unsigned b1) {
    asm volatile(
        "mma.sync.aligned.m16n8k16.row.col.f32.f16.f16.f32 "
        "{%0,%1,%2,%3}, {%4,%5,%6,%7}, {%8,%9}, {%0,%1,%2,%3};"
        : "+f"(c0), "+f"(c1), "+f"(c2), "+f"(c3)
        : "r"(a0), "r"(a1), "r"(a2), "r"(a3), "r"(b0), "r"(b1));
}

// ---------------------------------------------------------------------------
// node_y: per-node fp16 partials. Block 0 also: probes idx dtype, folds
// gamma/beta into g_fold (constant bank src), builds per-lane mma fragments.
// ---------------------------------------------------------------------------
__global__ void node_y_kernel(const float* __restrict__ x, long long n,
                              const void* __restrict__ ei, long long E,
                              const float* __restrict__ W1, const float* __restrict__ b1,
                              const float* __restrict__ g1, const float* __restrict__ be1,
                              const float* __restrict__ W2, const float* __restrict__ b2,
                              const float* __restrict__ g2, const float* __restrict__ be2,
                              const float* __restrict__ W3, const float* __restrict__ b3) {
    if (blockIdx.x == 0) {
        __shared__ int bad;
        if (threadIdx.x == 0) bad = 0;
        __syncthreads();
        {
            long long i = (long long)threadIdx.x;
            if (i < E && i < 256) {
                long long v = ((const long long*)ei)[i];
                if (v < 0 || v >= n) atomicAdd(&bad, 1);
            }
        }
        __syncthreads();
        if (threadIdx.x == 0) g_is64 = (bad == 0) ? 1 : 0;

        const int t = threadIdx.x;
        // constant-bank source (W1 attr rows + biases; full block kept for simplicity)
        for (int i = t; i < IN_DIM * HID; i += 256) g_fold[OW1 * 4 + i] = W1[i];
        if (t < HID) g_fold[OB1 * 4 + t] = b1[t];
        for (int i = t; i < HID * HID; i += 256) g_fold[OW2 * 4 + i] = W2[i] * g1[i / HID];
        if (t < HID) {
            float s = b2[t];
            #pragma unroll
            for (int i = 0; i < HID; i++) s += be1[i] * W2[i * HID + t];
            g_fold[OB2 * 4 + t] = s;
        }
        if (t < HID * ODIM) g_fold[OW3 * 4 + t] = W3[t] * g2[t / ODIM];
        if (t < ODIM) {
            float s = b3[t];
            #pragma unroll
            for (int i = 0; i < HID; i++) s += be2[i] * W3[i * ODIM + t];
            g_fold[OB3 * 4 + t] = s;
        }

        // per-lane mma fragments
        if (t < 32) {
            const int gid = t >> 2, tig = t & 3;
            const int k0 = tig * 2;
            // W2' (g1-folded) fp16 B fragments, col-major (k-major pairs)
            #define W2E(i, j) (W2[(i) * HID + (j)] * g1[(i)])
            uint4 v0, v1, v2;
            v0.x = packh2(W2E(k0,     gid),     W2E(k0 + 1, gid));
            v0.y = packh2(W2E(k0 + 8, gid),     W2E(k0 + 9, gid));
            v0.z = packh2(W2E(k0,     gid + 8), W2E(k0 + 1, gid + 8));
            v0.w = packh2(W2E(k0 + 8, gid + 8), W2E(k0 + 9, gid + 8));
            #undef W2E
            // W3' (g2-folded) fp16 B fragments, n padded to 8 (cols 4..7 = 0)
            #define W3E(i, j) (W3[(i) * ODIM + (j)] * g2[(i)])
            v1.x = (gid < 4) ? packh2(W3E(k0, gid),     W3E(k0 + 1, gid))  : 0u;
            v1.y = (gid < 4) ? packh2(W3E(k0 + 8, gid), W3E(k0 + 9, gid)) : 0u;
            #undef W3E
            // L2 bias (b2 + be1@W2) by col
            float bc[4];
            #pragma unroll
            for (int q = 0; q < 4; q++) {
                int col = ((q & 1) ? k0 + 1 : k0) + ((q & 2) ? 8 : 0);
                float s = b2[col];
                #pragma unroll
                for (int i = 0; i < HID; i++) s += be1[i] * W2[i * HID + col];
                bc[q] = s;
            }
            v1.z = __float_as_uint(bc[0]);
            v1.w = __float_as_uint(bc[1]);
            v2.x = __float_as_uint(bc[2]);
            v2.y = __float_as_uint(bc[3]);
            // L3 bias (b3 + be2@W3) by col (valid cols 0..3 -> tig<2)
            float b3c0 = 0.f, b3c1 = 0.f;
            if (tig < 2) {
                b3c0 = b3[k0]; b3c1 = b3[k0 + 1];
                #pragma unroll
                for (int i = 0; i < HID; i++) {
                    b3c0 += be2[i] * W3[i * ODIM + k0];
                    b3c1 += be2[i] * W3[i * ODIM + k0 + 1];
                }
            }
            v2.z = __float_as_uint(b3c0);
            v2.w = __float_as_uint(b3c1);
            g_wfrag[t * 4 + 0] = v0;
            g_wfrag[t * 4 + 1] = v1;
            g_wfrag[t * 4 + 2] = v2;
        }
    }

    long long idx = (long long)blockIdx.x * 256 + threadIdx.x;
    if (idx >= n || idx >= MAX_NODES) return;
    const float4* x4 = (const float4*)x;
    float4 a = x4[idx * 2], b = x4[idx * 2 + 1];
    float xv[8] = { a.x, a.y, a.z, a.w, b.x, b.y, b.z, b.w };

    float ya[16], yb[16];
    #pragma unroll
    for (int j = 0; j < 16; j++) { ya[j] = b1[j]; yb[j] = 0.0f; }
    #pragma unroll
    for (int i = 0; i < 8; i++) {
        #pragma unroll
        for (int j = 0; j < 16; j++) ya[j] = fmaf(xv[i], W1[i * HID + j], ya[j]);
        #pragma unroll
        for (int j = 0; j < 16; j++) yb[j] = fmaf(xv[i], W1[(8 + i) * HID + j], yb[j]);
    }
    uint4 ra0, ra1, rb0, rb1;
    unsigned* pa0 = (unsigned*)&ra0; unsigned* pa1 = (unsigned*)&ra1;
    unsigned* pb0 = (unsigned*)&rb0; unsigned* pb1 = (unsigned*)&rb1;
    #pragma unroll
    for (int q = 0; q < 4; q++) {
        pa0[q] = packh2(ya[2*q],     ya[2*q+1]);
        pa1[q] = packh2(ya[8+2*q],   ya[9+2*q]);
        pb0[q] = packh2(yb[2*q],     yb[2*q+1]);
        pb1[q] = packh2(yb[8+2*q],   yb[9+2*q]);
    }
    g_ya[idx*2] = ra0; g_ya[idx*2+1] = ra1;
    g_yb[idx*2] = rb0; g_yb[idx*2+1] = rb1;
}

// ReLU + un-affine LayerNorm, feature-packed (LN1 only)
__device__ __forceinline__ void relu_ln8(u64 (&h)[8]) {
    #pragma unroll
    for (int p = 0; p < 8; p++) h[p] = frelu2(h[p]);
    u64 s0 = fadd2(h[0], h[4]), s1 = fadd2(h[1], h[5]);
    u64 s2 = fadd2(h[2], h[6]), s3 = fadd2(h[3], h[7]);
    s0 = fadd2(s0, s2); s1 = fadd2(s1, s3);
    u64 s = fadd2(s0, s1);
    u64 q0 = fmul2(h[0], h[0]), q1 = fmul2(h[1], h[1]);
    u64 q2 = fmul2(h[2], h[2]), q3 = fmul2(h[3], h[3]);
    q0 = ffma2(h[4], h[4], q0); q1 = ffma2(h[5], h[5], q1);
    q2 = ffma2(h[6], h[6], q2); q3 = ffma2(h[7], h[7], q3);
    u64 q = fadd2(fadd2(q0, q1), fadd2(q2, q3));
    F2u su; su.u = s;
    F2u qu; qu.u = q;
    float tot  = su.f.x + su.f.y;
    float qtot = qu.f.x + qu.f.y;
    float mu  = tot * (1.0f / 16.0f);
    float var = fmaf(-mu, mu, qtot * (1.0f / 16.0f));
    float rs  = rsqrtf(var + LN_EPS);
    float c   = -mu * rs;
    u64 rsd = dupf(rs), cd = dupf(c);
    #pragma unroll
    for (int p = 0; p < 8; p++) h[p] = ffma2(h[p], rsd, cd);
}

// ---------------------------------------------------------------------------
// Main kernel: 1 edge/thread; layers 2+3 on tensor cores per warp.
// ---------------------------------------------------------------------------
__global__ __launch_bounds__(256, 4)
void edgeconv_kernel(
    const void*  __restrict__ ei,
    const float* __restrict__ attr,
    float* __restrict__ out,
    long long E)
{
    __shared__ unsigned hs[8][32][8];   // [warp][edge-in-warp][half2 pair]

    const int t = threadIdx.x;
    const int lane = t & 31;
    const int warp = t >> 5;
    const int gid = lane >> 2, tig = lane & 3;
    const long long warpBase = (long long)blockIdx.x * 256 + warp * 32;
    const long long tid = warpBase + lane;
    const long long e = (tid < E) ? tid : (E - 1);

    // weight fragments + biases (L1-hot table)
    uint4 v0 = g_wfrag[lane * 4 + 0];
    uint4 v1 = g_wfrag[lane * 4 + 1];
    uint4 v2 = g_wfrag[lane * 4 + 2];
    const float b2c0 = __uint_as_float(v1.z), b2c1 = __uint_as_float(v1.w);
    const float b2c2 = __uint_as_float(v2.x), b2c3 = __uint_as_float(v2.y);
    const float b3c0 = __uint_as_float(v2.z), b3c1 = __uint_as_float(v2.w);

    int f, to;
    if (g_is64) {
        const long long* p = (const long long*)ei;
        f = (int)p[e]; to = (int)p[E + e];
    } else {
        const int* p = (const int*)ei;
        f = p[e]; to = p[E + e];
    }

    uint4 ya0 = g_ya[(long long)f * 2],  ya1 = g_ya[(long long)f * 2 + 1];
    uint4 yb0 = g_yb[(long long)to * 2], yb1 = g_yb[(long long)to * 2 + 1];
    float4 at = ((const float4*)attr)[e];

    // ---- Layer 1: h = y_a[frm] + y_b[to] + attr @ W1c ----
    u64 h[8];
    {
        const unsigned* wa0 = (const unsigned*)&ya0;
        const unsigned* wa1 = (const unsigned*)&ya1;
        const unsigned* wb0 = (const unsigned*)&yb0;
        const unsigned* wb1 = (const unsigned*)&yb1;
        #pragma unroll
        for (int p = 0; p < 4; p++) h[p]     = fadd2(h2u(wa0[p]), h2u(wb0[p]));
        #pragma unroll
        for (int p = 0; p < 4; p++) h[4 + p] = fadd2(h2u(wa1[p]), h2u(wb1[p]));
    }
    #pragma unroll
    for (int i = 0; i < 4; i++) {
        const int rbase = OW1 + (16 + i) * 4;
        float4 q0 = cAll[rbase], q1 = cAll[rbase+1], q2 = cAll[rbase+2], q3 = cAll[rbase+3];
        u64 w[8] = { pk(q0.x,q0.y), pk(q0.z,q0.w), pk(q1.x,q1.y), pk(q1.z,q1.w),
                     pk(q2.x,q2.y), pk(q2.z,q2.w), pk(q3.x,q3.y), pk(q3.z,q3.w) };
        float av = (i == 0) ? at.x : (i == 1) ? at.y : (i == 2) ? at.z : at.w;
        u64 vd = dupf(av);
        #pragma unroll
        for (int p = 0; p < 8; p++) h[p] = ffma2(vd, w[p], h[p]);
    }

    relu_ln8(h);

    // ---- Stage activations (fp16) into smem for mma A fragments ----
    #pragma unroll
    for (int p = 0; p < 8; p++) {
        F2u x; x.u = h[p];
        hs[warp][lane][p] = packh2(x.f.x, x.f.y);
    }
    __syncwarp();

    // A fragments: M-tile0 = edges (lane rows) 0..15, M-tile1 = 16..31
    unsigned a0 = hs[warp][gid     ][tig];
    unsigned a1 = hs[warp][gid + 8 ][tig];
    unsigned a2 = hs[warp][gid     ][tig + 4];
    unsigned a3 = hs[warp][gid + 8 ][tig + 4];
    unsigned a4 = hs[warp][gid + 16][tig];
    unsigned a5 = hs[warp][gid + 24][tig];
    unsigned a6 = hs[warp][gid + 16][tig + 4];
    unsigned a7 = hs[warp][gid + 24][tig + 4];

    // ---- Layer 2: 4x mma (C init = bias by col) ----
    float cA0 = b2c0, cA1 = b2c1, cA2 = b2c0, cA3 = b2c1;   // M0,N0
    float cB0 = b2c2, cB1 = b2c3, cB2 = b2c2, cB3 = b2c3;   // M0,N1
    float cC0 = b2c0, cC1 = b2c1, cC2 = b2c0, cC3 = b2c1;   // M1,N0
    float cD0 = b2c2, cD1 = b2c3, cD2 = b2c2, cD3 = b2c3;   // M1,N1
    mma16816(cA0, cA1, cA2, cA3, a0, a1, a2, a3, v0.x, v0.y);
    mma16816(cB0, cB1, cB2, cB3, a0, a1, a2, a3, v0.z, v0.w);
    mma16816(cC0, cC1, cC2, cC3, a4, a5, a6, a7, v0.x, v0.y);
    mma16816(cD0, cD1, cD2, cD3, a4, a5, a6, a7, v0.z, v0.w);

    // ---- ReLU ----
    cA0 = fmaxf(cA0, 0.f); cA1 = fmaxf(cA1, 0.f); cA2 = fmaxf(cA2, 0.f); cA3 = fmaxf(cA3, 0.f);
    cB0 = fmaxf(cB0, 0.f); cB1 = fmaxf(cB1, 0.f); cB2 = fmaxf(cB2, 0.f); cB3 = fmaxf(cB3, 0.f);
    cC0 = fmaxf(cC0, 0.f); cC1 = fmaxf(cC1, 0.f); cC2 = fmaxf(cC2, 0.f); cC3 = fmaxf(cC3, 0.f);
    cD0 = fmaxf(cD0, 0.f); cD1 = fmaxf(cD1, 0.f); cD2 = fmaxf(cD2, 0.f); cD3 = fmaxf(cD3, 0.f);

    // ---- LN2 on distributed rows (4-lane group reduction) ----
    // row0=gid: cA0,cA1,cB0,cB1 ; row1=gid+8: cA2,cA3,cB2,cB3
    // row2=gid+16: cC0,cC1,cD0,cD1 ; row3=gid+24: cC2,cC3,cD2,cD3
    float s0 = cA0+cA1+cB0+cB1, q0 = cA0*cA0+cA1*cA1+cB0*cB0+cB1*cB1;
    float s1 = cA2+cA3+cB2+cB3, q1 = cA2*cA2+cA3*cA3+cB2*cB2+cB3*cB3;
    float s2 = cC0+cC1+cD0+cD1, q2 = cC0*cC0+cC1*cC1+cD0*cD0+cD1*cD1;
    float s3 = cC2+cC3+cD2+cD3, q3 = cC2*cC2+cC3*cC3+cD2*cD2+cD3*cD3;
    s0 += __shfl_xor_sync(0xffffffffu, s0, 1); s0 += __shfl_xor_sync(0xffffffffu, s0, 2);
    q0 += __shfl_xor_sync(0xffffffffu, q0, 1); q0 += __shfl_xor_sync(0xffffffffu, q0, 2);
    s1 += __shfl_xor_sync(0xffffffffu, s1, 1); s1 += __shfl_xor_sync(0xffffffffu, s1, 2);
    q1 += __shfl_xor_sync(0xffffffffu, q1, 1); q1 += __shfl_xor_sync(0xffffffffu, q1, 2);
    s2 += __shfl_xor_sync(0xffffffffu, s2, 1); s2 += __shfl_xor_sync(0xffffffffu, s2, 2);
    q2 += __shfl_xor_sync(0xffffffffu, q2, 1); q2 += __shfl_xor_sync(0xffffffffu, q2, 2);
    s3 += __shfl_xor_sync(0xffffffffu, s3, 1); s3 += __shfl_xor_sync(0xffffffffu, s3, 2);
    q3 += __shfl_xor_sync(0xffffffffu, q3, 1); q3 += __shfl_xor_sync(0xffffffffu, q3, 2);
    float mu0 = s0 * (1.f/16.f), rs0 = rsqrtf(fmaf(-mu0, mu0, q0 * (1.f/16.f)) + LN_EPS);
    float mu1 = s1 * (1.f/16.f), rs1 = rsqrtf(fmaf(-mu1, mu1, q1 * (1.f/16.f)) + LN_EPS);
    float mu2 = s2 * (1.f/16.f), rs2 = rsqrtf(fmaf(-mu2, mu2, q2 * (1.f/16.f)) + LN_EPS);
    float mu3 = s3 * (1.f/16.f), rs3 = rsqrtf(fmaf(-mu3, mu3, q3 * (1.f/16.f)) + LN_EPS);
    float n0 = -mu0 * rs0, n1 = -mu1 * rs1, n2 = -mu2 * rs2, n3 = -mu3 * rs3;
    cA0 = fmaf(cA0, rs0, n0); cA1 = fmaf(cA1, rs0, n0);
    cB0 = fmaf(cB0, rs0, n0); cB1 = fmaf(cB1, rs0, n0);
    cA2 = fmaf(cA2, rs1, n1); cA3 = fmaf(cA3, rs1, n1);
    cB2 = fmaf(cB2, rs1, n1); cB3 = fmaf(cB3, rs1, n1);
    cC0 = fmaf(cC0, rs2, n2); cC1 = fmaf(cC1, rs2, n2);
    cD0 = fmaf(cD0, rs2, n2); cD1 = fmaf(cD1, rs2, n2);
    cC2 = fmaf(cC2, rs3, n3); cC3 = fmaf(cC3, rs3, n3);
    cD2 = fmaf(cD2, rs3, n3); cD3 = fmaf(cD3, rs3, n3);

    // ---- Layer 3: C-frag layout == A-frag layout; 2x mma ----
    unsigned e0 = packh2(cA0, cA1);   // (row gid,    k tig*2..)
    unsigned e1 = packh2(cA2, cA3);   // (row gid+8)
    unsigned e2 = packh2(cB0, cB1);   // (row gid,    k tig*2+8..)
    unsigned e3 = packh2(cB2, cB3);
    unsigned e4 = packh2(cC0, cC1);
    unsigned e5 = packh2(cC2, cC3);
    unsigned e6 = packh2(cD0, cD1);
    unsigned e7 = packh2(cD2, cD3);

    float o00 = b3c0, o01 = b3c1, o02 = b3c0, o03 = b3c1;   // M0
    float o10 = b3c0, o11 = b3c1, o12 = b3c0, o13 = b3c1;   // M1
    mma16816(o00, o01, o02, o03, e0, e1, e2, e3, v1.x, v1.y);
    mma16816(o10, o11, o12, o13, e4, e5, e6, e7, v1.x, v1.y);

    // ---- Store: lanes with tig<2 hold valid output cols (0..3) ----
    if (tig < 2) {
        float2* o2 = (float2*)out;
        long long eg0 = warpBase + gid;
        long long eg1 = warpBase + gid + 8;
        long long eg2 = warpBase + gid + 16;
        long long eg3 = warpBase + gid + 24;
        if (eg0 < E) o2[eg0 * 2 + tig] = make_float2(o00, o01);
        if (eg1 < E) o2[eg1 * 2 + tig] = make_float2(o02, o03);
        if (eg2 < E) o2[eg2 * 2 + tig] = make_float2(o10, o11);
        if (eg3 < E) o2[eg3 * 2 + tig] = make_float2(o12, o13);
    }
}

extern "C" void kernel_launch(void* const* d_in, const int* in_sizes, int n_in,
                              void* d_out, int out_size) {
    const float* x    = (const float*)d_in[0];
    const void*  ei   = d_in[1];
    const float* attr = (const float*)d_in[2];
    const float* W1   = (const float*)d_in[3];
    const float* b1   = (const float*)d_in[4];
    const float* g1   = (const float*)d_in[5];
    const float* be1  = (const float*)d_in[6];
    const float* W2   = (const float*)d_in[7];
    const float* b2   = (const float*)d_in[8];
    const float* g2   = (const float*)d_in[9];
    const float* be2  = (const float*)d_in[10];
    const float* W3   = (const float*)d_in[11];
    const float* b3   = (const float*)d_in[12];
    float* out = (float*)d_out;

    const long long n_nodes = (long long)in_sizes[0] / 8;
    const long long E = (long long)in_sizes[2] / 4;   // edge_attr is [E,4]
    const int tpb = 256;
    const long long blocks = (E + tpb - 1) / tpb;

    // 1) per-node partials + dtype probe + folds + mma fragments (block 0)
    node_y_kernel<<<(unsigned)((n_nodes + 255) / 256), 256>>>(
        x, n_nodes, ei, E, W1, b1, g1, be1, W2, b2, g2, be2, W3, b3);

    // 2) fold scratch -> constant bank (d2d, graph-capturable)
    void* foldAddr = nullptr;
    cudaGetSymbolAddress(&foldAddr, g_fold);
    cudaMemcpyToSymbolAsync(cAll, foldAddr, CTOT * 4 * sizeof(float), 0,
                            cudaMemcpyDeviceToDevice, 0);

    // 3) main edge kernel
    edgeconv_kernel<<<(unsigned)blocks, tpb>>>(ei, attr, out, E);
}

// round 13
// speedup vs baseline: 1.2468x; 1.2468x over previous
#include <cuda_runtime.h>
#include <cuda_fp16.h>

// EdgeConv: per-edge MLP 20 -> 16 (ReLU+LN) -> 16 (ReLU+LN) -> 4, fp32.
// (R10 structure — best known.) 1 edge/thread, 128 tpb, occ 7.
// Per-node layer-1 partials y_a = x@W1[0:8]+b1, y_b = x@W1[8:16] precomputed
// fp16 by node_y_kernel (block 0 also probes idx dtype + folds gamma/beta).
// Weights in __constant__ (uniform port), trimmed to the used 1616B region.
// Graph: node_y -> memcpyToSymbol(1616B) -> main.

#define HID 16
#define IN_DIM 20
#define ODIM 4
#define LN_EPS 1e-5f
#define MAX_NODES 131072

// constant layout (float4 units) — only what the main kernel uses
#define OA  0           // W1 attr rows 16..19 : 64 floats = 16 float4
#define OB2 16          // b2 + be1@W2        : 16 floats = 4
#define OW2 20          // W2 * g1            : 256 floats = 64
#define OW3 84          // W3 * g2            : 64 floats = 16
#define OB3 100         // b3 + be2@W3        : 4 floats  = 1
#define CTOT 101

__constant__ float4 cAll[CTOT];
__device__ float g_fold[CTOT * 4];

// Per-node fp16 partials: 2 uint4 (32B) per node per side.
__device__ uint4 g_ya[MAX_NODES * 2];
__device__ uint4 g_yb[MAX_NODES * 2];
__device__ int g_is64;

typedef unsigned long long u64;
union F2u { float2 f; u64 u; };

__device__ __forceinline__ u64 pk(float lo, float hi) { F2u t; t.f.x = lo; t.f.y = hi; return t.u; }

__device__ __forceinline__ u64 dupf(float w) {
    u64 d; asm("mov.b64 %0, {%1, %1};" : "=l"(d) : "f"(w)); return d;
}
__device__ __forceinline__ u64 ffma2(u64 a, u64 b, u64 c) {
    u64 d; asm("fma.rn.f32x2 %0, %1, %2, %3;" : "=l"(d) : "l"(a), "l"(b), "l"(c)); return d;
}
__device__ __forceinline__ u64 fmul2(u64 a, u64 b) {
    u64 d; asm("mul.rn.f32x2 %0, %1, %2;" : "=l"(d) : "l"(a), "l"(b)); return d;
}
__device__ __forceinline__ u64 fadd2(u64 a, u64 b) {
    u64 d; asm("add.rn.f32x2 %0, %1, %2;" : "=l"(d) : "l"(a), "l"(b)); return d;
}
__device__ __forceinline__ u64 frelu2(u64 a) {
    F2u t; t.u = a; t.f.x = fmaxf(t.f.x, 0.f); t.f.y = fmaxf(t.f.y, 0.f); return t.u;
}

// ---------------------------------------------------------------------------
// node_y: per-node fp16 partials. Block 0 also probes the edge_index dtype
// and builds the trimmed folded-weight block in g_fold.
// ---------------------------------------------------------------------------
__global__ void node_y_kernel(const float* __restrict__ x, long long n,
                              const void* __restrict__ ei, long long E,
                              const float* __restrict__ W1, const float* __restrict__ b1,
                              const float* __restrict__ g1, const float* __restrict__ be1,
                              const float* __restrict__ W2, const float* __restrict__ b2,
                              const float* __restrict__ g2, const float* __restrict__ be2,
                              const float* __restrict__ W3, const float* __restrict__ b3) {
    if (blockIdx.x == 0) {
        __shared__ int bad;
        if (threadIdx.x == 0) bad = 0;
        __syncthreads();
        {
            long long i = (long long)threadIdx.x;
            if (i < E && i < 256) {
                long long v = ((const long long*)ei)[i];
                if (v < 0 || v >= n) atomicAdd(&bad, 1);
            }
        }
        __syncthreads();
        if (threadIdx.x == 0) g_is64 = (bad == 0) ? 1 : 0;

        const int t = threadIdx.x;
        // attr rows of W1 (rows 16..19), raw
        if (t < 4 * HID) g_fold[OA * 4 + t] = W1[16 * HID + t];
        // W2 * g1
        for (int i = t; i < HID * HID; i += 256) g_fold[OW2 * 4 + i] = W2[i] * g1[i / HID];
        // b2 + be1 @ W2
        if (t < HID) {
            float s = b2[t];
            #pragma unroll
            for (int i = 0; i < HID; i++) s += be1[i] * W2[i * HID + t];
            g_fold[OB2 * 4 + t] = s;
        }
        // W3 * g2
        if (t < HID * ODIM) g_fold[OW3 * 4 + t] = W3[t] * g2[t / ODIM];
        // b3 + be2 @ W3
        if (t < ODIM) {
            float s = b3[t];
            #pragma unroll
            for (int i = 0; i < HID; i++) s += be2[i] * W3[i * ODIM + t];
            g_fold[OB3 * 4 + t] = s;
        }
    }

    long long idx = (long long)blockIdx.x * 256 + threadIdx.x;
    if (idx >= n || idx >= MAX_NODES) return;
    const float4* x4 = (const float4*)x;
    float4 a = x4[idx * 2], b = x4[idx * 2 + 1];
    float xv[8] = { a.x, a.y, a.z, a.w, b.x, b.y, b.z, b.w };

    float ya[16], yb[16];
    #pragma unroll
    for (int j = 0; j < 16; j++) { ya[j] = b1[j]; yb[j] = 0.0f; }
    #pragma unroll
    for (int i = 0; i < 8; i++) {
        #pragma unroll
        for (int j = 0; j < 16; j++) ya[j] = fmaf(xv[i], W1[i * HID + j], ya[j]);
        #pragma unroll
        for (int j = 0; j < 16; j++) yb[j] = fmaf(xv[i], W1[(8 + i) * HID + j], yb[j]);
    }
    uint4 ra0, ra1, rb0, rb1;
    unsigned* pa0 = (unsigned*)&ra0; unsigned* pa1 = (unsigned*)&ra1;
    unsigned* pb0 = (unsigned*)&rb0; unsigned* pb1 = (unsigned*)&rb1;
    #pragma unroll
    for (int q = 0; q < 4; q++) {
        __half2 h = __floats2half2_rn(ya[2*q], ya[2*q+1]);
        pa0[q] = *(unsigned*)&h;
        __half2 h2 = __floats2half2_rn(ya[8+2*q], ya[9+2*q]);
        pa1[q] = *(unsigned*)&h2;
        __half2 h3 = __floats2half2_rn(yb[2*q], yb[2*q+1]);
        pb0[q] = *(unsigned*)&h3;
        __half2 h4 = __floats2half2_rn(yb[8+2*q], yb[9+2*q]);
        pb1[q] = *(unsigned*)&h4;
    }
    g_ya[idx*2] = ra0; g_ya[idx*2+1] = ra1;
    g_yb[idx*2] = rb0; g_yb[idx*2+1] = rb1;
}

// ReLU + un-affine LayerNorm on one feature-packed edge: h = (relu(h)-mu)*rs
__device__ __forceinline__ void relu_ln8(u64 (&h)[8]) {
    #pragma unroll
    for (int p = 0; p < 8; p++) h[p] = frelu2(h[p]);
    u64 s0 = fadd2(h[0], h[4]), s1 = fadd2(h[1], h[5]);
    u64 s2 = fadd2(h[2], h[6]), s3 = fadd2(h[3], h[7]);
    s0 = fadd2(s0, s2); s1 = fadd2(s1, s3);
    u64 s = fadd2(s0, s1);
    u64 q0 = fmul2(h[0], h[0]), q1 = fmul2(h[1], h[1]);
    u64 q2 = fmul2(h[2], h[2]), q3 = fmul2(h[3], h[3]);
    q0 = ffma2(h[4], h[4], q0); q1 = ffma2(h[5], h[5], q1);
    q2 = ffma2(h[6], h[6], q2); q3 = ffma2(h[7], h[7], q3);
    u64 q = fadd2(fadd2(q0, q1), fadd2(q2, q3));
    F2u su; su.u = s;
    F2u qu; qu.u = q;
    float tot  = su.f.x + su.f.y;
    float qtot = qu.f.x + qu.f.y;
    float mu  = tot * (1.0f / 16.0f);
    float var = fmaf(-mu, mu, qtot * (1.0f / 16.0f));
    float rs  = rsqrtf(var + LN_EPS);
    float c   = -mu * rs;
    u64 rsd = dupf(rs), cd = dupf(c);
    #pragma unroll
    for (int p = 0; p < 8; p++) h[p] = ffma2(h[p], rsd, cd);
}

__device__ __forceinline__ float lane16(const u64 (&h)[8], int i) {
    F2u t; t.u = h[i >> 1];
    return (i & 1) ? t.f.y : t.f.x;
}

// Convert half2 word -> packed f32x2 u64.
__device__ __forceinline__ u64 h2u(unsigned w) {
    __half2 h = *(__half2*)&w;
    float2 f = __half22float2(h);
    return pk(f.x, f.y);
}

// ---------------------------------------------------------------------------
// Main kernel: 1 edge/thread, fully coalesced edge-indexed accesses.
// ---------------------------------------------------------------------------
__global__ __launch_bounds__(128, 7)
void edgeconv_kernel(
    const void*  __restrict__ ei,
    const float* __restrict__ attr,
    float* __restrict__ out,
    long long E)
{
    const long long tid = (long long)blockIdx.x * 128 + threadIdx.x;
    const bool ok = (tid < E);
    const long long e = ok ? tid : (E - 1);

    int f, to;
    if (g_is64) {
        const long long* p = (const long long*)ei;
        f = (int)p[e]; to = (int)p[E + e];
    } else {
        const int* p = (const int*)ei;
        f = p[e]; to = p[E + e];
    }

    // Gathers: 2 LDG.128 per node side (fp16 partials), attr fp32 coalesced.
    uint4 ya0 = g_ya[(long long)f * 2],  ya1 = g_ya[(long long)f * 2 + 1];
    uint4 yb0 = g_yb[(long long)to * 2], yb1 = g_yb[(long long)to * 2 + 1];
    float4 at = ((const float4*)attr)[e];

    // ---- Layer 1: h = y_a[frm] + y_b[to] + attr @ W1c (bias inside y_a) ----
    u64 h[8];
    {
        const unsigned* wa0 = (const unsigned*)&ya0;
        const unsigned* wa1 = (const unsigned*)&ya1;
        const unsigned* wb0 = (const unsigned*)&yb0;
        const unsigned* wb1 = (const unsigned*)&yb1;
        #pragma unroll
        for (int p = 0; p < 4; p++) h[p]     = fadd2(h2u(wa0[p]), h2u(wb0[p]));
        #pragma unroll
        for (int p = 0; p < 4; p++) h[4 + p] = fadd2(h2u(wa1[p]), h2u(wb1[p]));
    }
    // attr rows (W1 rows 16..19)
    #pragma unroll
    for (int i = 0; i < 4; i++) {
        const int rbase = OA + i * 4;
        float4 q0 = cAll[rbase], q1 = cAll[rbase+1], q2 = cAll[rbase+2], q3 = cAll[rbase+3];
        u64 w[8] = { pk(q0.x,q0.y), pk(q0.z,q0.w), pk(q1.x,q1.y), pk(q1.z,q1.w),
                     pk(q2.x,q2.y), pk(q2.z,q2.w), pk(q3.x,q3.y), pk(q3.z,q3.w) };
        float av = (i == 0) ? at.x : (i == 1) ? at.y : (i == 2) ? at.z : at.w;
        u64 vd = dupf(av);
        #pragma unroll
        for (int p = 0; p < 8; p++) h[p] = ffma2(vd, w[p], h[p]);
    }

    relu_ln8(h);

    // ---- Layer 2: 16 -> 16 (g1/be1 folded) ----
    u64 h2[8];
    {
        float4 c0 = cAll[OB2], c1 = cAll[OB2+1], c2 = cAll[OB2+2], c3 = cAll[OB2+3];
        h2[0] = pk(c0.x,c0.y); h2[1] = pk(c0.z,c0.w);
        h2[2] = pk(c1.x,c1.y); h2[3] = pk(c1.z,c1.w);
        h2[4] = pk(c2.x,c2.y); h2[5] = pk(c2.z,c2.w);
        h2[6] = pk(c3.x,c3.y); h2[7] = pk(c3.z,c3.w);
    }
    #pragma unroll
    for (int i = 0; i < HID; i++) {
        const int rbase = OW2 + i * 4;
        float4 q0 = cAll[rbase], q1 = cAll[rbase+1], q2 = cAll[rbase+2], q3 = cAll[rbase+3];
        u64 vd = dupf(lane16(h, i));
        h2[0] = ffma2(vd, pk(q0.x,q0.y), h2[0]);
        h2[1] = ffma2(vd, pk(q0.z,q0.w), h2[1]);
        h2[2] = ffma2(vd, pk(q1.x,q1.y), h2[2]);
        h2[3] = ffma2(vd, pk(q1.z,q1.w), h2[3]);
        h2[4] = ffma2(vd, pk(q2.x,q2.y), h2[4]);
        h2[5] = ffma2(vd, pk(q2.z,q2.w), h2[5]);
        h2[6] = ffma2(vd, pk(q3.x,q3.y), h2[6]);
        h2[7] = ffma2(vd, pk(q3.z,q3.w), h2[7]);
    }

    relu_ln8(h2);

    // ---- Layer 3: 16 -> 4 (g2/be2 folded) ----
    u64 o0, o1;
    {
        float4 b = cAll[OB3];
        o0 = pk(b.x, b.y); o1 = pk(b.z, b.w);
    }
    #pragma unroll
    for (int i = 0; i < HID; i++) {
        float4 wq = cAll[OW3 + i];
        u64 vd = dupf(lane16(h2, i));
        o0 = ffma2(vd, pk(wq.x, wq.y), o0);
        o1 = ffma2(vd, pk(wq.z, wq.w), o1);
    }

    if (ok) {
        F2u a, b;
        a.u = o0; b.u = o1;
        ((float4*)out)[e] = make_float4(a.f.x, a.f.y, b.f.x, b.f.y);
    }
}

extern "C" void kernel_launch(void* const* d_in, const int* in_sizes, int n_in,
                              void* d_out, int out_size) {
    const float* x    = (const float*)d_in[0];
    const void*  ei   = d_in[1];
    const float* attr = (const float*)d_in[2];
    const float* W1   = (const float*)d_in[3];
    const float* b1   = (const float*)d_in[4];
    const float* g1   = (const float*)d_in[5];
    const float* be1  = (const float*)d_in[6];
    const float* W2   = (const float*)d_in[7];
    const float* b2   = (const float*)d_in[8];
    const float* g2   = (const float*)d_in[9];
    const float* be2  = (const float*)d_in[10];
    const float* W3   = (const float*)d_in[11];
    const float* b3   = (const float*)d_in[12];
    float* out = (float*)d_out;

    const long long n_nodes = (long long)in_sizes[0] / 8;
    const long long E = (long long)in_sizes[2] / 4;   // edge_attr is [E,4]
    const int tpb = 128;
    const long long blocks = (E + tpb - 1) / tpb;

    // 1) per-node layer-1 partials + dtype probe + gamma/beta fold (block 0)
    node_y_kernel<<<(unsigned)((n_nodes + 255) / 256), 256>>>(
        x, n_nodes, ei, E, W1, b1, g1, be1, W2, b2, g2, be2, W3, b3);

    // 2) fold scratch -> constant bank (d2d, graph-capturable, 1616B)
    void* foldAddr = nullptr;
    cudaGetSymbolAddress(&foldAddr, g_fold);
    cudaMemcpyToSymbolAsync(cAll, foldAddr, CTOT * 4 * sizeof(float), 0,
                            cudaMemcpyDeviceToDevice, 0);

    // 3) main edge kernel
    edgeconv_kernel<<<(unsigned)blocks, tpb>>>(ei, attr, out, E);
}

// round 14
// speedup vs baseline: 1.2793x; 1.0261x over previous
#include <cuda_runtime.h>
#include <cuda_fp16.h>

// EdgeConv: per-edge MLP 20 -> 16 (ReLU+LN) -> 16 (ReLU+LN) -> 4, fp32.
// R10 structure (best). 1 edge/thread, 128 tpb, occ 7.
// Layer-1 node terms via per-node fp16 partials (y_a = x@W1[0:8]+b1,
// y_b = x@W1[8:16]); y_a+y_b summed in HALF domain (8x HADD2) before a single
// conversion pass. Weights in __constant__ (uniform port, trimmed 1616B).
// Graph: node_y -> memcpyToSymbol -> main.

#define HID 16
#define IN_DIM 20
#define ODIM 4
#define LN_EPS 1e-5f
#define MAX_NODES 131072

// constant layout (float4 units)
#define OA  0           // W1 attr rows 16..19 : 16 float4
#define OB2 16          // b2 + be1@W2        : 4
#define OW2 20          // W2 * g1            : 64
#define OW3 84          // W3 * g2            : 16
#define OB3 100         // b3 + be2@W3        : 1
#define CTOT 101

__constant__ float4 cAll[CTOT];
__device__ float g_fold[CTOT * 4];

// Per-node fp16 partials: 2 uint4 (32B) per node per side.
__device__ uint4 g_ya[MAX_NODES * 2];
__device__ uint4 g_yb[MAX_NODES * 2];
__device__ int g_is64;

typedef unsigned long long u64;
union F2u { float2 f; u64 u; };

__device__ __forceinline__ u64 pk(float lo, float hi) { F2u t; t.f.x = lo; t.f.y = hi; return t.u; }

__device__ __forceinline__ u64 dupf(float w) {
    u64 d; asm("mov.b64 %0, {%1, %1};" : "=l"(d) : "f"(w)); return d;
}
__device__ __forceinline__ u64 ffma2(u64 a, u64 b, u64 c) {
    u64 d; asm("fma.rn.f32x2 %0, %1, %2, %3;" : "=l"(d) : "l"(a), "l"(b), "l"(c)); return d;
}
__device__ __forceinline__ u64 fmul2(u64 a, u64 b) {
    u64 d; asm("mul.rn.f32x2 %0, %1, %2;" : "=l"(d) : "l"(a), "l"(b)); return d;
}
__device__ __forceinline__ u64 fadd2(u64 a, u64 b) {
    u64 d; asm("add.rn.f32x2 %0, %1, %2;" : "=l"(d) : "l"(a), "l"(b)); return d;
}
__device__ __forceinline__ u64 frelu2(u64 a) {
    F2u t; t.u = a; t.f.x = fmaxf(t.f.x, 0.f); t.f.y = fmaxf(t.f.y, 0.f); return t.u;
}
__device__ __forceinline__ u64 h2u(unsigned w) {
    __half2 h = *(__half2*)&w;
    float2 f = __half22float2(h);
    return pk(f.x, f.y);
}

// ---------------------------------------------------------------------------
// node_y: per-node fp16 partials. Block 0 also probes the edge_index dtype
// and builds the trimmed folded-weight block in g_fold.
// ---------------------------------------------------------------------------
__global__ void node_y_kernel(const float* __restrict__ x, long long n,
                              const void* __restrict__ ei, long long E,
                              const float* __restrict__ W1, const float* __restrict__ b1,
                              const float* __restrict__ g1, const float* __restrict__ be1,
                              const float* __restrict__ W2, const float* __restrict__ b2,
                              const float* __restrict__ g2, const float* __restrict__ be2,
                              const float* __restrict__ W3, const float* __restrict__ b3) {
    if (blockIdx.x == 0) {
        __shared__ int bad;
        if (threadIdx.x == 0) bad = 0;
        __syncthreads();
        {
            long long i = (long long)threadIdx.x;
            if (i < E && i < 256) {
                long long v = ((const long long*)ei)[i];
                if (v < 0 || v >= n) atomicAdd(&bad, 1);
            }
        }
        __syncthreads();
        if (threadIdx.x == 0) g_is64 = (bad == 0) ? 1 : 0;

        const int t = threadIdx.x;
        if (t < 4 * HID) g_fold[OA * 4 + t] = W1[16 * HID + t];
        for (int i = t; i < HID * HID; i += 256) g_fold[OW2 * 4 + i] = W2[i] * g1[i / HID];
        if (t < HID) {
            float s = b2[t];
            #pragma unroll
            for (int i = 0; i < HID; i++) s += be1[i] * W2[i * HID + t];
            g_fold[OB2 * 4 + t] = s;
        }
        if (t < HID * ODIM) g_fold[OW3 * 4 + t] = W3[t] * g2[t / ODIM];
        if (t < ODIM) {
            float s = b3[t];
            #pragma unroll
            for (int i = 0; i < HID; i++) s += be2[i] * W3[i * ODIM + t];
            g_fold[OB3 * 4 + t] = s;
        }
    }

    long long idx = (long long)blockIdx.x * 256 + threadIdx.x;
    if (idx >= n || idx >= MAX_NODES) return;
    const float4* x4 = (const float4*)x;
    float4 a = x4[idx * 2], b = x4[idx * 2 + 1];
    float xv[8] = { a.x, a.y, a.z, a.w, b.x, b.y, b.z, b.w };

    float ya[16], yb[16];
    #pragma unroll
    for (int j = 0; j < 16; j++) { ya[j] = b1[j]; yb[j] = 0.0f; }
    #pragma unroll
    for (int i = 0; i < 8; i++) {
        #pragma unroll
        for (int j = 0; j < 16; j++) ya[j] = fmaf(xv[i], W1[i * HID + j], ya[j]);
        #pragma unroll
        for (int j = 0; j < 16; j++) yb[j] = fmaf(xv[i], W1[(8 + i) * HID + j], yb[j]);
    }
    uint4 ra0, ra1, rb0, rb1;
    unsigned* pa0 = (unsigned*)&ra0; unsigned* pa1 = (unsigned*)&ra1;
    unsigned* pb0 = (unsigned*)&rb0; unsigned* pb1 = (unsigned*)&rb1;
    #pragma unroll
    for (int q = 0; q < 4; q++) {
        __half2 h = __floats2half2_rn(ya[2*q], ya[2*q+1]);
        pa0[q] = *(unsigned*)&h;
        __half2 h2 = __floats2half2_rn(ya[8+2*q], ya[9+2*q]);
        pa1[q] = *(unsigned*)&h2;
        __half2 h3 = __floats2half2_rn(yb[2*q], yb[2*q+1]);
        pb0[q] = *(unsigned*)&h3;
        __half2 h4 = __floats2half2_rn(yb[8+2*q], yb[9+2*q]);
        pb1[q] = *(unsigned*)&h4;
    }
    g_ya[idx*2] = ra0; g_ya[idx*2+1] = ra1;
    g_yb[idx*2] = rb0; g_yb[idx*2+1] = rb1;
}

// ReLU + un-affine LayerNorm on one feature-packed edge: h = (relu(h)-mu)*rs
__device__ __forceinline__ void relu_ln8(u64 (&h)[8]) {
    #pragma unroll
    for (int p = 0; p < 8; p++) h[p] = frelu2(h[p]);
    u64 s0 = fadd2(h[0], h[4]), s1 = fadd2(h[1], h[5]);
    u64 s2 = fadd2(h[2], h[6]), s3 = fadd2(h[3], h[7]);
    s0 = fadd2(s0, s2); s1 = fadd2(s1, s3);
    u64 s = fadd2(s0, s1);
    u64 q0 = fmul2(h[0], h[0]), q1 = fmul2(h[1], h[1]);
    u64 q2 = fmul2(h[2], h[2]), q3 = fmul2(h[3], h[3]);
    q0 = ffma2(h[4], h[4], q0); q1 = ffma2(h[5], h[5], q1);
    q2 = ffma2(h[6], h[6], q2); q3 = ffma2(h[7], h[7], q3);
    u64 q = fadd2(fadd2(q0, q1), fadd2(q2, q3));
    F2u su; su.u = s;
    F2u qu; qu.u = q;
    float tot  = su.f.x + su.f.y;
    float qtot = qu.f.x + qu.f.y;
    float mu  = tot * (1.0f / 16.0f);
    float var = fmaf(-mu, mu, qtot * (1.0f / 16.0f));
    float rs  = rsqrtf(var + LN_EPS);
    float c   = -mu * rs;
    u64 rsd = dupf(rs), cd = dupf(c);
    #pragma unroll
    for (int p = 0; p < 8; p++) h[p] = ffma2(h[p], rsd, cd);
}

__device__ __forceinline__ float lane16(const u64 (&h)[8], int i) {
    F2u t; t.u = h[i >> 1];
    return (i & 1) ? t.f.y : t.f.x;
}

// ---------------------------------------------------------------------------
// Main kernel: 1 edge/thread, fully coalesced edge-indexed accesses.
// ---------------------------------------------------------------------------
__global__ __launch_bounds__(128, 7)
void edgeconv_kernel(
    const void*  __restrict__ ei,
    const float* __restrict__ attr,
    float* __restrict__ out,
    long long E)
{
    const long long tid = (long long)blockIdx.x * 128 + threadIdx.x;
    const bool ok = (tid < E);
    const long long e = ok ? tid : (E - 1);

    int f, to;
    if (g_is64) {
        const long long* p = (const long long*)ei;
        f = (int)p[e]; to = (int)p[E + e];
    } else {
        const int* p = (const int*)ei;
        f = p[e]; to = p[E + e];
    }

    // Gathers: 2 LDG.128 per node side (fp16 partials), attr fp32 coalesced.
    uint4 ya0 = g_ya[(long long)f * 2],  ya1 = g_ya[(long long)f * 2 + 1];
    uint4 yb0 = g_yb[(long long)to * 2], yb1 = g_yb[(long long)to * 2 + 1];
    float4 at = ((const float4*)attr)[e];

    // ---- Layer 1: h = (y_a[frm] (+h) y_b[to]) + attr @ W1c ----
    // Sum in half domain first (8 HADD2), single conversion pass after.
    u64 h[8];
    {
        const __half2* A0 = (const __half2*)&ya0;
        const __half2* A1 = (const __half2*)&ya1;
        const __half2* B0 = (const __half2*)&yb0;
        const __half2* B1 = (const __half2*)&yb1;
        #pragma unroll
        for (int p = 0; p < 4; p++) {
            __half2 s = __hadd2(A0[p], B0[p]);
            h[p] = h2u(*(unsigned*)&s);
        }
        #pragma unroll
        for (int p = 0; p < 4; p++) {
            __half2 s = __hadd2(A1[p], B1[p]);
            h[4 + p] = h2u(*(unsigned*)&s);
        }
    }
    // attr rows (W1 rows 16..19)
    #pragma unroll
    for (int i = 0; i < 4; i++) {
        const int rbase = OA + i * 4;
        float4 q0 = cAll[rbase], q1 = cAll[rbase+1], q2 = cAll[rbase+2], q3 = cAll[rbase+3];
        u64 w[8] = { pk(q0.x,q0.y), pk(q0.z,q0.w), pk(q1.x,q1.y), pk(q1.z,q1.w),
                     pk(q2.x,q2.y), pk(q2.z,q2.w), pk(q3.x,q3.y), pk(q3.z,q3.w) };
        float av = (i == 0) ? at.x : (i == 1) ? at.y : (i == 2) ? at.z : at.w;
        u64 vd = dupf(av);
        #pragma unroll
        for (int p = 0; p < 8; p++) h[p] = ffma2(vd, w[p], h[p]);
    }

    relu_ln8(h);

    // ---- Layer 2: 16 -> 16 (g1/be1 folded) ----
    u64 h2[8];
    {
        float4 c0 = cAll[OB2], c1 = cAll[OB2+1], c2 = cAll[OB2+2], c3 = cAll[OB2+3];
        h2[0] = pk(c0.x,c0.y); h2[1] = pk(c0.z,c0.w);
        h2[2] = pk(c1.x,c1.y); h2[3] = pk(c1.z,c1.w);
        h2[4] = pk(c2.x,c2.y); h2[5] = pk(c2.z,c2.w);
        h2[6] = pk(c3.x,c3.y); h2[7] = pk(c3.z,c3.w);
    }
    #pragma unroll
    for (int i = 0; i < HID; i++) {
        const int rbase = OW2 + i * 4;
        float4 q0 = cAll[rbase], q1 = cAll[rbase+1], q2 = cAll[rbase+2], q3 = cAll[rbase+3];
        u64 vd = dupf(lane16(h, i));
        h2[0] = ffma2(vd, pk(q0.x,q0.y), h2[0]);
        h2[1] = ffma2(vd, pk(q0.z,q0.w), h2[1]);
        h2[2] = ffma2(vd, pk(q1.x,q1.y), h2[2]);
        h2[3] = ffma2(vd, pk(q1.z,q1.w), h2[3]);
        h2[4] = ffma2(vd, pk(q2.x,q2.y), h2[4]);
        h2[5] = ffma2(vd, pk(q2.z,q2.w), h2[5]);
        h2[6] = ffma2(vd, pk(q3.x,q3.y), h2[6]);
        h2[7] = ffma2(vd, pk(q3.z,q3.w), h2[7]);
    }

    relu_ln8(h2);

    // ---- Layer 3: 16 -> 4 (g2/be2 folded) ----
    u64 o0, o1;
    {
        float4 b = cAll[OB3];
        o0 = pk(b.x, b.y); o1 = pk(b.z, b.w);
    }
    #pragma unroll
    for (int i = 0; i < HID; i++) {
        float4 wq = cAll[OW3 + i];
        u64 vd = dupf(lane16(h2, i));
        o0 = ffma2(vd, pk(wq.x, wq.y), o0);
        o1 = ffma2(vd, pk(wq.z, wq.w), o1);
    }

    if (ok) {
        F2u a, b;
        a.u = o0; b.u = o1;
        ((float4*)out)[e] = make_float4(a.f.x, a.f.y, b.f.x, b.f.y);
    }
}

extern "C" void kernel_launch(void* const* d_in, const int* in_sizes, int n_in,
                              void* d_out, int out_size) {
    const float* x    = (const float*)d_in[0];
    const void*  ei   = d_in[1];
    const float* attr = (const float*)d_in[2];
    const float* W1   = (const float*)d_in[3];
    const float* b1   = (const float*)d_in[4];
    const float* g1   = (const float*)d_in[5];
    const float* be1  = (const float*)d_in[6];
    const float* W2   = (const float*)d_in[7];
    const float* b2   = (const float*)d_in[8];
    const float* g2   = (const float*)d_in[9];
    const float* be2  = (const float*)d_in[10];
    const float* W3   = (const float*)d_in[11];
    const float* b3   = (const float*)d_in[12];
    float* out = (float*)d_out;

    const long long n_nodes = (long long)in_sizes[0] / 8;
    const long long E = (long long)in_sizes[2] / 4;   // edge_attr is [E,4]
    const int tpb = 128;
    const long long blocks = (E + tpb - 1) / tpb;

    // 1) per-node layer-1 partials + dtype probe + gamma/beta fold (block 0)
    node_y_kernel<<<(unsigned)((n_nodes + 255) / 256), 256>>>(
        x, n_nodes, ei, E, W1, b1, g1, be1, W2, b2, g2, be2, W3, b3);

    // 2) fold scratch -> constant bank (d2d, graph-capturable)
    void* foldAddr = nullptr;
    cudaGetSymbolAddress(&foldAddr, g_fold);
    cudaMemcpyToSymbolAsync(cAll, foldAddr, CTOT * 4 * sizeof(float), 0,
                            cudaMemcpyDeviceToDevice, 0);

    // 3) main edge kernel
    edgeconv_kernel<<<(unsigned)blocks, tpb>>>(ei, attr, out, E);
}